// round 10
// baseline (speedup 1.0000x reference)
#include <cuda_runtime.h>
#include <cuda_fp16.h>
#include <cstdint>
#include <math.h>

#define BATCH 64
#define CH    32
#define HH    128
#define WW    128
#define PAD   130
#define EPSV  1e-5f
#define HW    (HH * WW)

// conv1 activations: padded NHWC fp16 pair-permuted (16 u32/px); borders zero
__device__ uint32_t g_a2[(size_t)BATCH * PAD * PAD * 16];

__device__ __host__ __forceinline__ int pos8(int p) {
    return ((p & 3) << 1) | ((p >> 2) & 1);
}
__device__ __forceinline__ uint32_t h2_as_u32(__half2 h) {
    return *reinterpret_cast<uint32_t*>(&h);
}
__device__ __forceinline__ void mma_f16(float c[4],
                                        uint32_t a0, uint32_t a1, uint32_t a2, uint32_t a3,
                                        uint32_t b0, uint32_t b1) {
    asm volatile(
        "mma.sync.aligned.m16n8k16.row.col.f32.f16.f16.f32 "
        "{%0,%1,%2,%3}, {%4,%5,%6,%7}, {%8,%9}, {%0,%1,%2,%3};"
        : "+f"(c[0]), "+f"(c[1]), "+f"(c[2]), "+f"(c[3])
        : "r"(a0), "r"(a1), "r"(a2), "r"(a3), "r"(b0), "r"(b1));
}

// B^T d B butterfly (exact +/- arithmetic, fp32)
__device__ __forceinline__ void wino_bt(const float d[4][4], float W[4][4]) {
    float e[4][4];
    #pragma unroll
    for (int j = 0; j < 4; j++) {
        e[0][j] = d[0][j] - d[2][j];
        e[1][j] = d[1][j] + d[2][j];
        e[2][j] = d[2][j] - d[1][j];
        e[3][j] = d[1][j] - d[3][j];
    }
    #pragma unroll
    for (int i = 0; i < 4; i++) {
        W[i][0] = e[i][0] - e[i][2];
        W[i][1] = e[i][1] + e[i][2];
        W[i][2] = e[i][2] - e[i][1];
        W[i][3] = e[i][1] - e[i][3];
    }
}

// ---- smem layout (u32 units) ----
#define RSTRIDE 24
#define RSLOT   (34 * RSTRIDE)     // 816 per raw row (34 px)
#define RAW0    0                  // 10 rows staged -> 8160 used; region 8192
#define D0      8192               // 16 pts x 64 tiles x 16 u32 (xor-swizzled) = 16384
#define U0      24576              // 16 pts x 2 q x 32 co x 8 u32 = 8192
#define C0      32768              // consts: SS1 TT1 SS2 TT2 (32 fp each)
#define SNF     (C0 + 128)         // 32896 u32
#define SMEMB   (SNF * 4)          // 131584 B -> 1 CTA/SM

__global__ void border_kernel() {
    int i = blockIdx.x * 256 + threadIdx.x;
    if (i >= BATCH * 516 * 4) return;
    int f4 = i & 3;
    int t  = i >> 2;
    int p  = t % 516;
    int b  = t / 516;
    int yp, xp;
    if      (p < 130) { yp = 0;       xp = p; }
    else if (p < 260) { yp = PAD - 1; xp = p - 130; }
    else if (p < 388) { yp = p - 259; xp = 0; }
    else              { yp = p - 387; xp = PAD - 1; }
    uint4* d = (uint4*)(g_a2 + (((size_t)b * PAD + yp) * PAD + xp) * 16);
    d[f4] = make_uint4(0u, 0u, 0u, 0u);
}

// MODE 0: x NCHW --(bn1+relu+fp16)--> wino conv1 --(b1+bn2+relu fp16)--> g_a2
// MODE 1: g_a2   --(copy)----------> wino conv2 --(b2 + residual)-----> out NCHW
template <int MODE>
__global__ void __launch_bounds__(256)
conv_kernel(const void* __restrict__ srcv,
            const float* __restrict__ w,
            const float* __restrict__ bias,
            const float* __restrict__ g1, const float* __restrict__ be1,
            const float* __restrict__ m1, const float* __restrict__ v1,
            const float* __restrict__ g2, const float* __restrict__ be2,
            const float* __restrict__ m2, const float* __restrict__ v2,
            const float* __restrict__ resid,
            void* __restrict__ dstv)
{
    extern __shared__ uint32_t sm[];
    uint32_t* RawS = sm + RAW0;
    uint32_t* Dd   = sm + D0;
    uint32_t* Uu   = sm + U0;
    float* SS1 = (float*)(sm + C0);
    float* TT1 = (float*)(sm + C0 + 32);
    float* SS2 = (float*)(sm + C0 + 64);
    float* TT2 = (float*)(sm + C0 + 96);

    const int tid = threadIdx.x;
    const int x0  = blockIdx.x * 32;
    const int y0  = blockIdx.y * 8;
    const int b   = blockIdx.z;

    // consts
    if (MODE == 0) {
        if (tid < 32) {
            float sc = g1[tid] * rsqrtf(v1[tid] + EPSV);
            SS1[tid] = sc;
            TT1[tid] = be1[tid] - m1[tid] * sc;
        } else if (tid < 64) {
            int c = tid - 32;
            float sc = g2[c] * rsqrtf(v2[c] + EPSV);
            SS2[c] = sc;
            TT2[c] = bias[c] * sc + (be2[c] - m2[c] * sc);
        }
    } else {
        if (tid < 32) SS2[tid] = bias[tid];   // plain bias for MODE1 epilogue
    }
    __syncthreads();

    // ---- stage raw input: 10 rows x 34 px x 16 u32 (fp16 pair-permuted) ----
    if (MODE == 0) {
        const float* xb0 = (const float*)srcv + (size_t)b * CH * HW;
        for (int i = tid; i < 10 * 16 * 34; i += 256) {
            int s   = i / 544;
            int rem = i - s * 544;
            int j   = rem / 34;
            int px  = rem - j * 34;
            int yin = y0 - 1 + s;
            int gx  = x0 - 1 + px;
            int q   = j >> 3;
            int jj  = j & 7;
            int pl  = ((jj & 1) << 2) | (jj >> 1);
            int c0  = (q * 8 + pl) * 2;
            int c1  = c0 + 1;
            uint32_t val = 0u;
            if ((unsigned)yin < (unsigned)HH && (unsigned)gx < (unsigned)WW) {
                const float* p = xb0 + (size_t)yin * WW + gx;
                float v0 = fmaxf(p[(size_t)c0 * HW] * SS1[c0] + TT1[c0], 0.f);
                float v1 = fmaxf(p[(size_t)c1 * HW] * SS1[c1] + TT1[c1], 0.f);
                val = h2_as_u32(__floats2half2_rn(v0, v1));
            }
            RawS[s * RSLOT + px * RSTRIDE + j] = val;
        }
    } else {
        const uint32_t* srcb = (const uint32_t*)srcv + (((size_t)b * PAD + y0) * PAD + x0) * 16;
        for (int i = tid; i < 10 * 34 * 4; i += 256) {
            int s  = i / 136;
            int j  = i - s * 136;
            int px = j >> 2;
            int f4 = j & 3;
            uint4 v = ((const uint4*)(srcb + (size_t)s * PAD * 16))[px * 4 + f4];
            *(uint4*)(RawS + s * RSLOT + px * RSTRIDE + f4 * 4) = v;
        }
    }

    // ---- weight transform: U[t][q][co][8] fp16 (G g G^T in fp32) ----
    {
        __half* Uh = (__half*)Uu;
        #pragma unroll 1
        for (int it = 0; it < 4; it++) {
            int co = tid & 31;
            int ci = it * 8 + (tid >> 5);
            float gm[3][3];
            const float* wp = w + co * 288 + ci * 9;
            #pragma unroll
            for (int r = 0; r < 3; r++)
                #pragma unroll
                for (int c = 0; c < 3; c++) gm[r][c] = wp[r * 3 + c];
            float m[4][3];
            #pragma unroll
            for (int c = 0; c < 3; c++) {
                m[0][c] = gm[0][c];
                m[1][c] = 0.5f * (gm[0][c] + gm[1][c] + gm[2][c]);
                m[2][c] = 0.5f * (gm[0][c] - gm[1][c] + gm[2][c]);
                m[3][c] = gm[2][c];
            }
            int q   = ci >> 4;
            int pl  = (ci >> 1) & 7;
            int lo  = ci & 1;
            #pragma unroll
            for (int i4 = 0; i4 < 4; i4++) {
                float u0 = m[i4][0];
                float u1 = 0.5f * (m[i4][0] + m[i4][1] + m[i4][2]);
                float u2 = 0.5f * (m[i4][0] - m[i4][1] + m[i4][2]);
                float u3 = m[i4][2];
                float uv[4] = {u0, u1, u2, u3};
                #pragma unroll
                for (int j4 = 0; j4 < 4; j4++) {
                    int t = i4 * 4 + j4;
                    int bidx = ((t * 2 + q) * 32 + co) * 8 + pos8(pl);
                    Uh[bidx * 2 + lo] = __float2half_rn(uv[j4]);
                }
            }
        }
    }
    __syncthreads();

    // ---- input transform: raw -> D[t][tile][16 u32 ^ swz] ----
    {
        int j  = tid & 15;
        int tx = tid >> 4;                 // 0..15
        #pragma unroll 1
        for (int ty = 0; ty < 4; ty++) {
            int tile = ty * 16 + tx;
            float dl[4][4], dh[4][4];
            #pragma unroll
            for (int i = 0; i < 4; i++)
                #pragma unroll
                for (int jj = 0; jj < 4; jj++) {
                    uint32_t u = RawS[(ty * 2 + i) * RSLOT + (tx * 2 + jj) * RSTRIDE + j];
                    __half2 h = *(__half2*)&u;
                    float2 f = __half22float2(h);
                    dl[i][jj] = f.x;
                    dh[i][jj] = f.y;
                }
            float Wl[4][4], Wh[4][4];
            wino_bt(dl, Wl);
            wino_bt(dh, Wh);
            int swz = (tile & 3) << 2;
            uint32_t* dt = Dd + tile * 16 + (j ^ swz);
            #pragma unroll
            for (int i = 0; i < 4; i++)
                #pragma unroll
                for (int jj = 0; jj < 4; jj++)
                    dt[(i * 4 + jj) * 1024] = h2_as_u32(__floats2half2_rn(Wl[i][jj], Wh[i][jj]));
        }
    }
    __syncthreads();

    // ---- GEMM over 16 transform points + in-register output transform ----
    const int lane = tid & 31;
    const int warp = tid >> 5;
    const int g    = lane >> 2;
    const int tig  = lane & 3;
    const int Mt   = warp & 3;           // tile row (ty)
    const int nh   = warp >> 2;          // co half

    float Y[4][2][4];                    // [oi*2+oj][n][k]
    #pragma unroll
    for (int a = 0; a < 4; a++)
        #pragma unroll
        for (int n = 0; n < 2; n++)
            #pragma unroll
            for (int k = 0; k < 4; k++) Y[a][n][k] = 0.f;

    const uint32_t* abase = Dd + (Mt * 16 + g) * 16;
    const int swz = (g & 3) << 2;
    const int ia0 = (0 * 8 + 2 * tig) ^ swz;
    const int ia1 = (1 * 8 + 2 * tig) ^ swz;
    const int ATc[2][4] = {{1, 1, 1, 0}, {0, 1, -1, -1}};

    #pragma unroll
    for (int t = 0; t < 16; t++) {
        float C[2][4] = {{0.f, 0.f, 0.f, 0.f}, {0.f, 0.f, 0.f, 0.f}};
        #pragma unroll
        for (int q = 0; q < 2; q++) {
            const uint32_t* ap = abase + t * 1024 + (q ? ia1 : ia0);
            uint2 lo = *(const uint2*)ap;
            uint2 hi = *(const uint2*)(ap + 128);
            #pragma unroll
            for (int n = 0; n < 2; n++) {
                uint2 bb = *(const uint2*)(Uu + (((t * 2 + q) * 32) + nh * 16 + n * 8 + g) * 8 + 2 * tig);
                mma_f16(C[n], lo.x, hi.x, lo.y, hi.y, bb.x, bb.y);
            }
        }
        const int ti = t >> 2, tj = t & 3;
        #pragma unroll
        for (int oi = 0; oi < 2; oi++) {
            const int cei = ATc[oi][ti];
            if (cei == 0) continue;
            #pragma unroll
            for (int oj = 0; oj < 2; oj++) {
                const int cej = ATc[oj][tj];
                if (cej == 0) continue;
                const int cc = cei * cej;
                #pragma unroll
                for (int n = 0; n < 2; n++)
                    #pragma unroll
                    for (int k = 0; k < 4; k++)
                        Y[oi * 2 + oj][n][k] += (cc > 0) ? C[n][k] : -C[n][k];
            }
        }
    }

    // ---- epilogue ----
    if (MODE == 0) {
        uint32_t* Os = sm;                 // [256 px][20 u32] overlays raw
        #pragma unroll
        for (int h2i = 0; h2i < 2; h2i++) {
            const int txp = g + 8 * h2i;
            #pragma unroll
            for (int n = 0; n < 2; n++) {
                const int co = nh * 16 + n * 8 + 2 * tig;
                const int pr = co >> 1;
                const int pos = (pr & 8) + pos8(pr & 7);
                float s0 = SS2[co],     t0 = TT2[co];
                float s1 = SS2[co + 1], t1 = TT2[co + 1];
                #pragma unroll
                for (int oi = 0; oi < 2; oi++)
                    #pragma unroll
                    for (int oj = 0; oj < 2; oj++) {
                        float v0 = fmaxf(Y[oi * 2 + oj][n][h2i * 2 + 0] * s0 + t0, 0.f);
                        float v1 = fmaxf(Y[oi * 2 + oj][n][h2i * 2 + 1] * s1 + t1, 0.f);
                        int px = (Mt * 2 + oi) * 32 + txp * 2 + oj;
                        Os[px * 20 + pos] = h2_as_u32(__floats2half2_rn(v0, v1));
                    }
            }
        }
        __syncthreads();
        uint32_t* d0 = (uint32_t*)dstv + (((size_t)b * PAD + (y0 + 1)) * PAD + (x0 + 1)) * 16;
        for (int i = tid; i < 1024; i += 256) {
            int py  = i >> 7;
            int rem = i & 127;
            int pxx = rem >> 2;
            int f4  = rem & 3;
            uint4 v = *(const uint4*)(Os + (py * 32 + pxx) * 20 + f4 * 4);
            *(uint4*)(d0 + (size_t)py * PAD * 16 + (size_t)pxx * 16 + f4 * 4) = v;
        }
    } else {
        float* Os32 = (float*)sm;          // [256 px][32 co xor-swizzled]
        #pragma unroll
        for (int h2i = 0; h2i < 2; h2i++) {
            const int txp = g + 8 * h2i;
            #pragma unroll
            for (int n = 0; n < 2; n++) {
                #pragma unroll
                for (int kk = 0; kk < 2; kk++) {
                    const int co = nh * 16 + n * 8 + 2 * tig + kk;
                    #pragma unroll
                    for (int oi = 0; oi < 2; oi++)
                        #pragma unroll
                        for (int oj = 0; oj < 2; oj++) {
                            int px = (Mt * 2 + oi) * 32 + txp * 2 + oj;
                            Os32[px * 32 + (co ^ ((px & 7) << 2))] = Y[oi * 2 + oj][n][h2i * 2 + kk];
                        }
                }
            }
        }
        __syncthreads();
        float* dst = (float*)dstv;
        for (int it = 0; it < 32; it++) {
            int i    = it * 256 + tid;
            int pxx8 = i & 7;
            int co   = (i >> 3) & 31;
            int blk  = i >> 8;
            int px   = blk * 8 + pxx8;
            int y    = y0 + (px >> 5);
            int x    = x0 + (px & 31);
            size_t o = ((size_t)(b * CH + co) * HH + y) * WW + x;
            dst[o] = Os32[px * 32 + (co ^ ((px & 7) << 2))] + SS2[co] + resid[o];
        }
    }
}

// ---- launch ----
extern "C" void kernel_launch(void* const* d_in, const int* in_sizes, int n_in,
                              void* d_out, int out_size)
{
    const float* x         = (const float*)d_in[0];
    const float* bn1_gamma = (const float*)d_in[1];
    const float* bn1_beta  = (const float*)d_in[2];
    const float* bn1_mean  = (const float*)d_in[3];
    const float* bn1_var   = (const float*)d_in[4];
    const float* w1        = (const float*)d_in[5];
    const float* b1        = (const float*)d_in[6];
    const float* bn2_gamma = (const float*)d_in[7];
    const float* bn2_beta  = (const float*)d_in[8];
    const float* bn2_mean  = (const float*)d_in[9];
    const float* bn2_var   = (const float*)d_in[10];
    const float* w2        = (const float*)d_in[11];
    const float* b2        = (const float*)d_in[12];
    float* out = (float*)d_out;

    void* a2p = nullptr;
    cudaGetSymbolAddress(&a2p, g_a2);

    cudaFuncSetAttribute(conv_kernel<0>, cudaFuncAttributeMaxDynamicSharedMemorySize, SMEMB);
    cudaFuncSetAttribute(conv_kernel<1>, cudaFuncAttributeMaxDynamicSharedMemorySize, SMEMB);

    border_kernel<<<(BATCH * 516 * 4 + 255) / 256, 256>>>();

    dim3 grid(WW / 32, HH / 8, BATCH);   // (4, 16, 64)

    conv_kernel<0><<<grid, 256, SMEMB>>>(x, w1, b1,
                                         bn1_gamma, bn1_beta, bn1_mean, bn1_var,
                                         bn2_gamma, bn2_beta, bn2_mean, bn2_var,
                                         nullptr, a2p);

    conv_kernel<1><<<grid, 256, SMEMB>>>(a2p, w2, b2,
                                         nullptr, nullptr, nullptr, nullptr,
                                         nullptr, nullptr, nullptr, nullptr,
                                         x, out);
}

// round 11
// speedup vs baseline: 1.3222x; 1.3222x over previous
#include <cuda_runtime.h>
#include <cuda_fp16.h>
#include <cstdint>
#include <math.h>

#define BATCH 64
#define CH    32
#define HH    128
#define WW    128
#define PAD   130
#define EPSV  1e-5f
#define HW    (HH * WW)

// conv1 activations: padded NHWC fp16 pair-permuted (16 u32/px); borders zero
__device__ uint32_t g_a2[(size_t)BATCH * PAD * PAD * 16];

__device__ __host__ __forceinline__ int pos8(int p) {
    return ((p & 3) << 1) | ((p >> 2) & 1);
}
__device__ __forceinline__ uint32_t h2_as_u32(__half2 h) {
    return *reinterpret_cast<uint32_t*>(&h);
}
__device__ __forceinline__ void mma_f16(float c[4],
                                        uint32_t a0, uint32_t a1, uint32_t a2, uint32_t a3,
                                        uint32_t b0, uint32_t b1) {
    asm volatile(
        "mma.sync.aligned.m16n8k16.row.col.f32.f16.f16.f32 "
        "{%0,%1,%2,%3}, {%4,%5,%6,%7}, {%8,%9}, {%0,%1,%2,%3};"
        : "+f"(c[0]), "+f"(c[1]), "+f"(c[2]), "+f"(c[3])
        : "r"(a0), "r"(a1), "r"(a2), "r"(a3), "r"(b0), "r"(b1));
}

// B^T d B butterfly (exact +/- arithmetic, fp32)
__device__ __forceinline__ void wino_bt(const float d[4][4], float W[4][4]) {
    float e[4][4];
    #pragma unroll
    for (int j = 0; j < 4; j++) {
        e[0][j] = d[0][j] - d[2][j];
        e[1][j] = d[1][j] + d[2][j];
        e[2][j] = d[2][j] - d[1][j];
        e[3][j] = d[1][j] - d[3][j];
    }
    #pragma unroll
    for (int i = 0; i < 4; i++) {
        W[i][0] = e[i][0] - e[i][2];
        W[i][1] = e[i][1] + e[i][2];
        W[i][2] = e[i][2] - e[i][1];
        W[i][3] = e[i][1] - e[i][3];
    }
}

// ---- smem layout (u32 units) ----
// phase 1: [raw 8192 | D 16384 | consts]
// phase 2+ (U overlays raw):  [U 8192 | D 16384 | consts]
// epilogue: Os overlays U region (after post-GEMM sync)
#define RSTRIDE 24
#define RSLOT   (34 * RSTRIDE)     // 816 per raw row (34 px)
#define RAW0    0
#define D0      8192
#define U0      0
#define C0      24576
#define SNF     (C0 + 128)         // 24704 u32
#define SMEMB   (SNF * 4)          // 98816 B -> 2 CTAs/SM

__global__ void border_kernel() {
    int i = blockIdx.x * 256 + threadIdx.x;
    if (i >= BATCH * 516 * 4) return;
    int f4 = i & 3;
    int t  = i >> 2;
    int p  = t % 516;
    int b  = t / 516;
    int yp, xp;
    if      (p < 130) { yp = 0;       xp = p; }
    else if (p < 260) { yp = PAD - 1; xp = p - 130; }
    else if (p < 388) { yp = p - 259; xp = 0; }
    else              { yp = p - 387; xp = PAD - 1; }
    uint4* d = (uint4*)(g_a2 + (((size_t)b * PAD + yp) * PAD + xp) * 16);
    d[f4] = make_uint4(0u, 0u, 0u, 0u);
}

// MODE 0: x NCHW --(bn1+relu+fp16)--> wino conv1 --(b1+bn2+relu fp16)--> g_a2
// MODE 1: g_a2   --(copy)----------> wino conv2 --(b2 + residual)-----> out NCHW
template <int MODE>
__global__ void __launch_bounds__(256, 2)
conv_kernel(const void* __restrict__ srcv,
            const float* __restrict__ w,
            const float* __restrict__ bias,
            const float* __restrict__ g1, const float* __restrict__ be1,
            const float* __restrict__ m1, const float* __restrict__ v1,
            const float* __restrict__ g2, const float* __restrict__ be2,
            const float* __restrict__ m2, const float* __restrict__ v2,
            const float* __restrict__ resid,
            void* __restrict__ dstv)
{
    extern __shared__ uint32_t sm[];
    uint32_t* RawS = sm + RAW0;
    uint32_t* Dd   = sm + D0;
    uint32_t* Uu   = sm + U0;
    float* SS1 = (float*)(sm + C0);
    float* TT1 = (float*)(sm + C0 + 32);
    float* SS2 = (float*)(sm + C0 + 64);
    float* TT2 = (float*)(sm + C0 + 96);

    const int tid = threadIdx.x;
    const int x0  = blockIdx.x * 32;
    const int y0  = blockIdx.y * 8;
    const int b   = blockIdx.z;

    // consts
    if (MODE == 0) {
        if (tid < 32) {
            float sc = g1[tid] * rsqrtf(v1[tid] + EPSV);
            SS1[tid] = sc;
            TT1[tid] = be1[tid] - m1[tid] * sc;
        } else if (tid < 64) {
            int c = tid - 32;
            float sc = g2[c] * rsqrtf(v2[c] + EPSV);
            SS2[c] = sc;
            TT2[c] = bias[c] * sc + (be2[c] - m2[c] * sc);
        }
    } else {
        if (tid < 32) SS2[tid] = bias[tid];
    }
    __syncthreads();

    // ---- phase 1: stage raw input: 10 rows x 34 px x 16 u32 ----
    if (MODE == 0) {
        const float* xb0 = (const float*)srcv + (size_t)b * CH * HW;
        for (int i = tid; i < 10 * 16 * 34; i += 256) {
            int s   = i / 544;
            int rem = i - s * 544;
            int j   = rem / 34;
            int px  = rem - j * 34;
            int yin = y0 - 1 + s;
            int gx  = x0 - 1 + px;
            int q   = j >> 3;
            int jj  = j & 7;
            int pl  = ((jj & 1) << 2) | (jj >> 1);
            int c0  = (q * 8 + pl) * 2;
            int c1  = c0 + 1;
            uint32_t val = 0u;
            if ((unsigned)yin < (unsigned)HH && (unsigned)gx < (unsigned)WW) {
                const float* p = xb0 + (size_t)yin * WW + gx;
                float v0 = fmaxf(p[(size_t)c0 * HW] * SS1[c0] + TT1[c0], 0.f);
                float v1 = fmaxf(p[(size_t)c1 * HW] * SS1[c1] + TT1[c1], 0.f);
                val = h2_as_u32(__floats2half2_rn(v0, v1));
            }
            RawS[s * RSLOT + px * RSTRIDE + j] = val;
        }
    } else {
        const uint32_t* srcb = (const uint32_t*)srcv + (((size_t)b * PAD + y0) * PAD + x0) * 16;
        for (int i = tid; i < 10 * 34 * 4; i += 256) {
            int s  = i / 136;
            int j  = i - s * 136;
            int px = j >> 2;
            int f4 = j & 3;
            uint4 v = ((const uint4*)(srcb + (size_t)s * PAD * 16))[px * 4 + f4];
            *(uint4*)(RawS + s * RSLOT + px * RSTRIDE + f4 * 4) = v;
        }
    }
    __syncthreads();

    // ---- phase 2: input transform: raw -> D[t][tile][16 u32 ^ swz] ----
    {
        int j  = tid & 15;
        int tx = tid >> 4;                 // 0..15
        #pragma unroll 1
        for (int ty = 0; ty < 4; ty++) {
            int tile = ty * 16 + tx;
            float dl[4][4], dh[4][4];
            #pragma unroll
            for (int i = 0; i < 4; i++)
                #pragma unroll
                for (int jj = 0; jj < 4; jj++) {
                    uint32_t u = RawS[(ty * 2 + i) * RSLOT + (tx * 2 + jj) * RSTRIDE + j];
                    __half2 h = *(__half2*)&u;
                    float2 f = __half22float2(h);
                    dl[i][jj] = f.x;
                    dh[i][jj] = f.y;
                }
            float Wl[4][4], Wh[4][4];
            wino_bt(dl, Wl);
            wino_bt(dh, Wh);
            int swz = (tile & 3) << 2;
            uint32_t* dt = Dd + tile * 16 + (j ^ swz);
            #pragma unroll
            for (int i = 0; i < 4; i++)
                #pragma unroll
                for (int jj = 0; jj < 4; jj++)
                    dt[(i * 4 + jj) * 1024] = h2_as_u32(__floats2half2_rn(Wl[i][jj], Wh[i][jj]));
        }
    }
    __syncthreads();   // raw fully consumed; U may now overlay it

    // ---- phase 3: weight transform: U[t][q][co][8] fp16 over raw region ----
    {
        __half* Uh = (__half*)Uu;
        #pragma unroll 1
        for (int it = 0; it < 4; it++) {
            int co = tid & 31;
            int ci = it * 8 + (tid >> 5);
            float gm[3][3];
            const float* wp = w + co * 288 + ci * 9;
            #pragma unroll
            for (int r = 0; r < 3; r++)
                #pragma unroll
                for (int c = 0; c < 3; c++) gm[r][c] = wp[r * 3 + c];
            float m[4][3];
            #pragma unroll
            for (int c = 0; c < 3; c++) {
                m[0][c] = gm[0][c];
                m[1][c] = 0.5f * (gm[0][c] + gm[1][c] + gm[2][c]);
                m[2][c] = 0.5f * (gm[0][c] - gm[1][c] + gm[2][c]);
                m[3][c] = gm[2][c];
            }
            int q   = ci >> 4;
            int pl  = (ci >> 1) & 7;
            int lo  = ci & 1;
            #pragma unroll
            for (int i4 = 0; i4 < 4; i4++) {
                float u0 = m[i4][0];
                float u1 = 0.5f * (m[i4][0] + m[i4][1] + m[i4][2]);
                float u2 = 0.5f * (m[i4][0] - m[i4][1] + m[i4][2]);
                float u3 = m[i4][2];
                float uv[4] = {u0, u1, u2, u3};
                #pragma unroll
                for (int j4 = 0; j4 < 4; j4++) {
                    int t = i4 * 4 + j4;
                    int bidx = ((t * 2 + q) * 32 + co) * 8 + pos8(pl);
                    Uh[bidx * 2 + lo] = __float2half_rn(uv[j4]);
                }
            }
        }
    }
    __syncthreads();

    // ---- phase 4: GEMM over 16 points, incremental A^T.M.A in fp32 regs ----
    const int lane = tid & 31;
    const int warp = tid >> 5;
    const int g    = lane >> 2;
    const int tig  = lane & 3;
    const int Mt   = warp & 3;           // tile row (ty)
    const int nh   = warp >> 2;          // co half

    float Y[4][2][4];                    // [oi*2+oj][n][k]
    #pragma unroll
    for (int a = 0; a < 4; a++)
        #pragma unroll
        for (int n = 0; n < 2; n++)
            #pragma unroll
            for (int k = 0; k < 4; k++) Y[a][n][k] = 0.f;

    const uint32_t* abase = Dd + (Mt * 16 + g) * 16;
    const int swz = (g & 3) << 2;
    const int ia0 = (0 * 8 + 2 * tig) ^ swz;
    const int ia1 = (1 * 8 + 2 * tig) ^ swz;

    #pragma unroll 1
    for (int ti = 0; ti < 4; ti++) {
        // A^T row coefficients for this ti (runtime floats, folded via FFMA)
        float c0 = (ti < 3)  ? 1.f : 0.f;                       // oi = 0
        float c1 = (ti == 0) ? 0.f : ((ti == 1) ? 1.f : -1.f);  // oi = 1
        #pragma unroll
        for (int tj = 0; tj < 4; tj++) {
            const int t = ti * 4 + tj;
            float C[2][4] = {{0.f, 0.f, 0.f, 0.f}, {0.f, 0.f, 0.f, 0.f}};
            #pragma unroll
            for (int q = 0; q < 2; q++) {
                const uint32_t* ap = abase + t * 1024 + (q ? ia1 : ia0);
                uint2 lo = *(const uint2*)ap;
                uint2 hi = *(const uint2*)(ap + 128);
                #pragma unroll
                for (int n = 0; n < 2; n++) {
                    uint2 bb = *(const uint2*)(Uu + (((t * 2 + q) * 32) + nh * 16 + n * 8 + g) * 8 + 2 * tig);
                    mma_f16(C[n], lo.x, hi.x, lo.y, hi.y, bb.x, bb.y);
                }
            }
            // oj = 0 : cej = +1 for tj<3
            if (tj < 3) {
                #pragma unroll
                for (int n = 0; n < 2; n++)
                    #pragma unroll
                    for (int k = 0; k < 4; k++) {
                        Y[0][n][k] = fmaf(c0, C[n][k], Y[0][n][k]);
                        Y[2][n][k] = fmaf(c1, C[n][k], Y[2][n][k]);
                    }
            }
            // oj = 1 : cej = +1 (tj=1), -1 (tj=2,3); static sign folds into -C
            if (tj > 0) {
                #pragma unroll
                for (int n = 0; n < 2; n++)
                    #pragma unroll
                    for (int k = 0; k < 4; k++) {
                        float cv = (tj == 1) ? C[n][k] : -C[n][k];
                        Y[1][n][k] = fmaf(c0, cv, Y[1][n][k]);
                        Y[3][n][k] = fmaf(c1, cv, Y[3][n][k]);
                    }
            }
        }
    }
    __syncthreads();   // U fully consumed; Os may overlay it

    // ---- epilogue ----
    if (MODE == 0) {
        uint32_t* Os = sm;                 // [256 px][20 u32] overlays U/raw
        #pragma unroll
        for (int h2i = 0; h2i < 2; h2i++) {
            const int txp = g + 8 * h2i;
            #pragma unroll
            for (int n = 0; n < 2; n++) {
                const int co = nh * 16 + n * 8 + 2 * tig;
                const int pr = co >> 1;
                const int pos = (pr & 8) + pos8(pr & 7);
                float s0 = SS2[co],     t0 = TT2[co];
                float s1 = SS2[co + 1], t1 = TT2[co + 1];
                #pragma unroll
                for (int oi = 0; oi < 2; oi++)
                    #pragma unroll
                    for (int oj = 0; oj < 2; oj++) {
                        float v0 = fmaxf(Y[oi * 2 + oj][n][h2i * 2 + 0] * s0 + t0, 0.f);
                        float v1 = fmaxf(Y[oi * 2 + oj][n][h2i * 2 + 1] * s1 + t1, 0.f);
                        int px = (Mt * 2 + oi) * 32 + txp * 2 + oj;
                        Os[px * 20 + pos] = h2_as_u32(__floats2half2_rn(v0, v1));
                    }
            }
        }
        __syncthreads();
        uint32_t* d0 = (uint32_t*)dstv + (((size_t)b * PAD + (y0 + 1)) * PAD + (x0 + 1)) * 16;
        for (int i = tid; i < 1024; i += 256) {
            int py  = i >> 7;
            int rem = i & 127;
            int pxx = rem >> 2;
            int f4  = rem & 3;
            uint4 v = *(const uint4*)(Os + (py * 32 + pxx) * 20 + f4 * 4);
            *(uint4*)(d0 + (size_t)py * PAD * 16 + (size_t)pxx * 16 + f4 * 4) = v;
        }
    } else {
        float* Os32 = (float*)sm;          // [256 px][32 co xor-swizzled] = 8192 u32
        #pragma unroll
        for (int h2i = 0; h2i < 2; h2i++) {
            const int txp = g + 8 * h2i;
            #pragma unroll
            for (int n = 0; n < 2; n++) {
                #pragma unroll
                for (int kk = 0; kk < 2; kk++) {
                    const int co = nh * 16 + n * 8 + 2 * tig + kk;
                    #pragma unroll
                    for (int oi = 0; oi < 2; oi++)
                        #pragma unroll
                        for (int oj = 0; oj < 2; oj++) {
                            int px = (Mt * 2 + oi) * 32 + txp * 2 + oj;
                            Os32[px * 32 + (co ^ ((px & 7) << 2))] = Y[oi * 2 + oj][n][h2i * 2 + kk];
                        }
                }
            }
        }
        __syncthreads();
        float* dst = (float*)dstv;
        for (int it = 0; it < 32; it++) {
            int i    = it * 256 + tid;
            int pxx8 = i & 7;
            int co   = (i >> 3) & 31;
            int blk  = i >> 8;
            int px   = blk * 8 + pxx8;
            int y    = y0 + (px >> 5);
            int x    = x0 + (px & 31);
            size_t o = ((size_t)(b * CH + co) * HH + y) * WW + x;
            dst[o] = Os32[px * 32 + (co ^ ((px & 7) << 2))] + SS2[co] + resid[o];
        }
    }
}

// ---- launch ----
extern "C" void kernel_launch(void* const* d_in, const int* in_sizes, int n_in,
                              void* d_out, int out_size)
{
    const float* x         = (const float*)d_in[0];
    const float* bn1_gamma = (const float*)d_in[1];
    const float* bn1_beta  = (const float*)d_in[2];
    const float* bn1_mean  = (const float*)d_in[3];
    const float* bn1_var   = (const float*)d_in[4];
    const float* w1        = (const float*)d_in[5];
    const float* b1        = (const float*)d_in[6];
    const float* bn2_gamma = (const float*)d_in[7];
    const float* bn2_beta  = (const float*)d_in[8];
    const float* bn2_mean  = (const float*)d_in[9];
    const float* bn2_var   = (const float*)d_in[10];
    const float* w2        = (const float*)d_in[11];
    const float* b2        = (const float*)d_in[12];
    float* out = (float*)d_out;

    void* a2p = nullptr;
    cudaGetSymbolAddress(&a2p, g_a2);

    cudaFuncSetAttribute(conv_kernel<0>, cudaFuncAttributeMaxDynamicSharedMemorySize, SMEMB);
    cudaFuncSetAttribute(conv_kernel<1>, cudaFuncAttributeMaxDynamicSharedMemorySize, SMEMB);

    border_kernel<<<(BATCH * 516 * 4 + 255) / 256, 256>>>();

    dim3 grid(WW / 32, HH / 8, BATCH);   // (4, 16, 64)

    conv_kernel<0><<<grid, 256, SMEMB>>>(x, w1, b1,
                                         bn1_gamma, bn1_beta, bn1_mean, bn1_var,
                                         bn2_gamma, bn2_beta, bn2_mean, bn2_var,
                                         nullptr, a2p);

    conv_kernel<1><<<grid, 256, SMEMB>>>(a2p, w2, b2,
                                         nullptr, nullptr, nullptr, nullptr,
                                         nullptr, nullptr, nullptr, nullptr,
                                         x, out);
}

// round 12
// speedup vs baseline: 2.9386x; 2.2225x over previous
#include <cuda_runtime.h>
#include <cuda_fp16.h>
#include <cstdint>
#include <math.h>

#define BATCH 64
#define CH    32
#define HH    128
#define WW    128
#define PAD   130
#define EPSV  1e-5f
#define RROWS 4
#define HW    (HH * WW)

// conv1 activations: padded NHWC, half2 channel-pairs in permuted positions; borders zero
// per pixel: 16 u32 (=32 fp16 channels)
__device__ uint32_t g_a2[(size_t)BATCH * PAD * PAD * 16];

// pair permutation within an 8-pair chunk: pair p stored at position 2*(p&3) + (p>>2)
__device__ __host__ __forceinline__ int pos8(int p) {
    return ((p & 3) << 1) | ((p >> 2) & 1);
}

__device__ __forceinline__ uint32_t h2_as_u32(__half2 h) {
    return *reinterpret_cast<uint32_t*>(&h);
}

__device__ __forceinline__ void mma_f16(float c[4],
                                        uint32_t a0, uint32_t a1, uint32_t a2, uint32_t a3,
                                        uint32_t b0, uint32_t b1) {
    asm volatile(
        "mma.sync.aligned.m16n8k16.row.col.f32.f16.f16.f32 "
        "{%0,%1,%2,%3}, {%4,%5,%6,%7}, {%8,%9}, {%0,%1,%2,%3};"
        : "+f"(c[0]), "+f"(c[1]), "+f"(c[2]), "+f"(c[3])
        : "r"(a0), "r"(a1), "r"(a2), "r"(a3), "r"(b0), "r"(b1));
}

// ---- smem layout (u32 units) ----
#define ASTRIDE 24                    // 16 data + 8 pad per pixel
#define ASLOT   (66 * ASTRIDE)        // 1584
#define ANF     (6 * ASLOT)           // 9504
#define BNF     (9 * 2 * 32 * 8)      // 4608  [tap][q][co][8]
#define OFF_SS1 (ANF + BNF)           // 14112
#define OFF_TT1 (OFF_SS1 + 32)
#define OFF_SS2 (OFF_TT1 + 32)
#define OFF_TT2 (OFF_SS2 + 32)
#define SNF     (OFF_TT2 + 32)        // 14240 u32
#define SMEMB   (SNF * 4)             // 56960 B
// MODE0 epilogue staging reuses As region: 256 px * 20 u32 = 5120 u32

// zero borders of g_a2 (516 border px per batch, 4 uint4 each)
__global__ void border_kernel() {
    int i = blockIdx.x * 256 + threadIdx.x;     // over 64*516*4
    if (i >= BATCH * 516 * 4) return;
    int f4 = i & 3;
    int t  = i >> 2;
    int p  = t % 516;
    int b  = t / 516;
    int yp, xp;
    if      (p < 130) { yp = 0;       xp = p; }
    else if (p < 260) { yp = PAD - 1; xp = p - 130; }
    else if (p < 388) { yp = p - 259; xp = 0; }
    else              { yp = p - 387; xp = PAD - 1; }
    uint4* d = (uint4*)(g_a2 + (((size_t)b * PAD + yp) * PAD + xp) * 16);
    d[f4] = make_uint4(0u, 0u, 0u, 0u);
}

// MODE 0: x NCHW --(bn1+relu+fp16 staged)--> conv1 --(b1+bn2+relu, fp16)--> g_a2
// MODE 1: g_a2   --(copy staged)----------> conv2 --(b2 + residual x)----> out NCHW
template <int MODE>
__global__ void __launch_bounds__(256, 2)
conv_kernel(const void* __restrict__ srcv,
            const float* __restrict__ w,
            const float* __restrict__ bias,
            const float* __restrict__ g1, const float* __restrict__ be1,
            const float* __restrict__ m1, const float* __restrict__ v1,
            const float* __restrict__ g2, const float* __restrict__ be2,
            const float* __restrict__ m2, const float* __restrict__ v2,
            const float* __restrict__ resid,
            void* __restrict__ dstv)
{
    extern __shared__ uint32_t sm[];
    uint32_t* As  = sm;
    uint32_t* Bs  = sm + ANF;
    float* SS1 = (float*)(sm + OFF_SS1);
    float* TT1 = (float*)(sm + OFF_TT1);
    float* SS2 = (float*)(sm + OFF_SS2);
    float* TT2 = (float*)(sm + OFF_TT2);

    const int tid = threadIdx.x;
    const int x0  = blockIdx.x * 64;
    const int y0  = blockIdx.y * RROWS;
    const int b   = blockIdx.z;

    if (MODE == 0) {
        if (tid < 32) {
            float sc = g1[tid] * rsqrtf(v1[tid] + EPSV);
            SS1[tid] = sc;
            TT1[tid] = be1[tid] - m1[tid] * sc;
        } else if (tid < 64) {
            int c = tid - 32;
            float sc = g2[c] * rsqrtf(v2[c] + EPSV);
            SS2[c] = sc;
            TT2[c] = bias[c] * sc + (be2[c] - m2[c] * sc);
        }
        __syncthreads();
    }

    // ---- stage weights as fp16: Bs[((tap*2+q)*32+co)*8 + pos], half idx *2 + (ci&1) ----
    {
        __half* Bh = (__half*)Bs;
        for (int i = tid; i < CH * CH * 9; i += 256) {
            int co  = i / 288;
            int rem = i - co * 288;
            int ci  = rem / 9;
            int tap = rem - ci * 9;
            int q   = ci >> 4;
            int pl  = (ci >> 1) & 7;
            int idx = ((tap * 2 + q) * 32 + co) * 8 + pos8(pl);
            Bh[idx * 2 + (ci & 1)] = __float2half_rn(w[i]);
        }
    }

    // ---- stage 6 input rows x 66 px x 16 u32 ----
    if (MODE == 0) {
        const float* xb0 = (const float*)srcv + (size_t)b * CH * HW;
        for (int i = tid; i < 6 * 16 * 66; i += 256) {
            int s   = i / 1056;
            int rem = i - s * 1056;
            int j   = rem / 66;              // storage position 0..15
            int px  = rem - j * 66;
            int yin = y0 - 1 + s;
            int gx  = x0 - 1 + px;
            int q   = j >> 3;
            int jj  = j & 7;
            int pl  = ((jj & 1) << 2) | (jj >> 1);
            int c0  = (q * 8 + pl) * 2;
            int c1  = c0 + 1;
            uint32_t val = 0u;
            if ((unsigned)yin < (unsigned)HH && (unsigned)gx < (unsigned)WW) {
                const float* p = xb0 + (size_t)yin * WW + gx;
                float v0 = fmaxf(p[(size_t)c0 * HW] * SS1[c0] + TT1[c0], 0.f);
                float v1 = fmaxf(p[(size_t)c1 * HW] * SS1[c1] + TT1[c1], 0.f);
                val = h2_as_u32(__floats2half2_rn(v0, v1));
            }
            As[s * ASLOT + px * ASTRIDE + j] = val;
        }
    } else {
        const uint32_t* srcb = (const uint32_t*)srcv + (((size_t)b * PAD + y0) * PAD + x0) * 16;
        for (int i = tid; i < 6 * 66 * 4; i += 256) {      // uint4 granularity
            int s = i / 264;
            int j = i - s * 264;
            int px = j >> 2;
            int f4 = j & 3;
            uint4 v = ((const uint4*)(srcb + (size_t)s * PAD * 16))[px * 4 + f4];
            *(uint4*)(As + s * ASLOT + px * ASTRIDE + f4 * 4) = v;
        }
    }
    __syncthreads();

    // ---- MMA mainloop ----
    const int lane = tid & 31;
    const int warp = tid >> 5;
    const int g    = lane >> 2;
    const int tig  = lane & 3;
    const int r    = warp >> 1;          // output row 0..3
    const int xh   = (warp & 1) * 32;

    float C[2][4][4];
    #pragma unroll
    for (int mt = 0; mt < 2; mt++)
        #pragma unroll
        for (int n = 0; n < 4; n++)
            #pragma unroll
            for (int k = 0; k < 4; k++) C[mt][n][k] = 0.f;

    #pragma unroll 1
    for (int ky = 0; ky < 3; ky++) {
        #pragma unroll 1
        for (int kx = 0; kx < 3; kx++) {
            const int tap = ky * 3 + kx;
            uint32_t bq[2][4][2];
            #pragma unroll
            for (int q = 0; q < 2; q++)
                #pragma unroll
                for (int n = 0; n < 4; n++) {
                    uint2 bb = *(const uint2*)(Bs + (((tap * 2 + q) * 32) + n * 8 + g) * 8 + 2 * tig);
                    bq[q][n][0] = bb.x;
                    bq[q][n][1] = bb.y;
                }
            const uint32_t* Arow = As + (r + ky) * ASLOT + kx * ASTRIDE;
            #pragma unroll
            for (int mt = 0; mt < 2; mt++) {
                const int xb = xh + mt * 16;
                #pragma unroll
                for (int q = 0; q < 2; q++) {
                    const uint32_t* ap = Arow + (xb + g) * ASTRIDE + q * 8 + 2 * tig;
                    uint2 a02 = *(const uint2*)ap;                       // pixel xb+g
                    uint2 a13 = *(const uint2*)(ap + 8 * ASTRIDE);       // pixel xb+g+8
                    #pragma unroll
                    for (int n = 0; n < 4; n++)
                        mma_f16(C[mt][n], a02.x, a13.x, a02.y, a13.y,
                                bq[q][n][0], bq[q][n][1]);
                }
            }
        }
    }

    // ---- epilogue ----
    if (MODE == 0) {
        __syncthreads();
        uint32_t* Os = sm;                // [256 px][20 u32]
        const int pr = r * 64;
        #pragma unroll
        for (int mt = 0; mt < 2; mt++) {
            const int xb = xh + mt * 16;
            #pragma unroll
            for (int n = 0; n < 4; n++) {
                const int co = n * 8 + 2 * tig;
                const int p  = n * 4 + tig;                       // pair index
                const int pos = ((p >> 3) << 3) + pos8(p & 7);
                float s0 = SS2[co],     t0 = TT2[co];
                float s1 = SS2[co + 1], t1 = TT2[co + 1];
                float v0 = fmaxf(C[mt][n][0] * s0 + t0, 0.f);
                float v1 = fmaxf(C[mt][n][1] * s1 + t1, 0.f);
                float v2 = fmaxf(C[mt][n][2] * s0 + t0, 0.f);
                float v3 = fmaxf(C[mt][n][3] * s1 + t1, 0.f);
                Os[(pr + xb + g) * 20 + pos]     = h2_as_u32(__floats2half2_rn(v0, v1));
                Os[(pr + xb + g + 8) * 20 + pos] = h2_as_u32(__floats2half2_rn(v2, v3));
            }
        }
        __syncthreads();
        // 4 rows * 64 px * 4 uint4 = 1024 uint4, coalesced
        uint32_t* d0 = (uint32_t*)dstv + (((size_t)b * PAD + (y0 + 1)) * PAD + (x0 + 1)) * 16;
        for (int i = tid; i < 1024; i += 256) {
            int rr  = i >> 8;
            int rem = i & 255;
            int pxl = rem >> 2;
            int f4  = rem & 3;
            uint4 v = *(const uint4*)(Os + (rr * 64 + pxl) * 20 + f4 * 4);
            *(uint4*)(d0 + (size_t)rr * PAD * 16 + (size_t)pxl * 16 + f4 * 4) = v;
        }
    } else {
        float* dst = (float*)dstv;
        const int y = y0 + r;
        #pragma unroll
        for (int mt = 0; mt < 2; mt++) {
            const int xb = xh + mt * 16;
            #pragma unroll
            for (int n = 0; n < 4; n++) {
                const int co = n * 8 + 2 * tig;
                float bb0 = bias[co], bb1 = bias[co + 1];
                size_t o00 = (((size_t)b * CH + co)     * HH + y) * WW + (x0 + xb + g);
                size_t o01 = (((size_t)b * CH + co + 1) * HH + y) * WW + (x0 + xb + g);
                dst[o00]     = C[mt][n][0] + bb0 + resid[o00];
                dst[o01]     = C[mt][n][1] + bb1 + resid[o01];
                dst[o00 + 8] = C[mt][n][2] + bb0 + resid[o00 + 8];
                dst[o01 + 8] = C[mt][n][3] + bb1 + resid[o01 + 8];
            }
        }
    }
}

// ---- launch ----
extern "C" void kernel_launch(void* const* d_in, const int* in_sizes, int n_in,
                              void* d_out, int out_size)
{
    const float* x         = (const float*)d_in[0];
    const float* bn1_gamma = (const float*)d_in[1];
    const float* bn1_beta  = (const float*)d_in[2];
    const float* bn1_mean  = (const float*)d_in[3];
    const float* bn1_var   = (const float*)d_in[4];
    const float* w1        = (const float*)d_in[5];
    const float* b1        = (const float*)d_in[6];
    const float* bn2_gamma = (const float*)d_in[7];
    const float* bn2_beta  = (const float*)d_in[8];
    const float* bn2_mean  = (const float*)d_in[9];
    const float* bn2_var   = (const float*)d_in[10];
    const float* w2        = (const float*)d_in[11];
    const float* b2        = (const float*)d_in[12];
    float* out = (float*)d_out;

    void* a2p = nullptr;
    cudaGetSymbolAddress(&a2p, g_a2);

    cudaFuncSetAttribute(conv_kernel<0>, cudaFuncAttributeMaxDynamicSharedMemorySize, SMEMB);
    cudaFuncSetAttribute(conv_kernel<1>, cudaFuncAttributeMaxDynamicSharedMemorySize, SMEMB);

    border_kernel<<<(BATCH * 516 * 4 + 255) / 256, 256>>>();

    dim3 grid(2, HH / RROWS, BATCH);   // (2, 32, 64)

    conv_kernel<0><<<grid, 256, SMEMB>>>(x, w1, b1,
                                         bn1_gamma, bn1_beta, bn1_mean, bn1_var,
                                         bn2_gamma, bn2_beta, bn2_mean, bn2_var,
                                         nullptr, a2p);

    conv_kernel<1><<<grid, 256, SMEMB>>>(a2p, w2, b2,
                                         nullptr, nullptr, nullptr, nullptr,
                                         nullptr, nullptr, nullptr, nullptr,
                                         x, out);
}